// round 5
// baseline (speedup 1.0000x reference)
#include <cuda_runtime.h>
#include <math.h>

#define NCTA 128
#define NTHR 256
#define Bb 256      // batch
#define Ss 512      // seq len
#define Ii 256      // input dim
#define Hh 512      // hidden dim
#define BBd 256     // backbone dim
#define Oo 128      // out dim

// shared memory: weights only (activations now stream via LDG)
#define P1   772    // pitch stage1 weight rows (K=768 + pad), 16B-aligned (772*4)
#define PB   260    // pitch backbone/head weight rows (K=256 + pad)

#define OFF_W1  0
#define SZ_W1   (16 * P1)          // 12352
#define OFF_WB  (OFF_W1 + SZ_W1)
#define SZ_WB   (48 * PB)          // 12480
#define OFF_WH  (OFF_WB + SZ_WB)
#define SZ_WH   (64 * PB)          // 16640
#define SMEM_FLOATS (OFF_WH + SZ_WH)     // 41472 floats
#define SMEM_BYTES  (SMEM_FLOATS * 4)    // 165888 B

typedef unsigned long long u64;

// ---------------- device scratch (static globals: allocation-free) ----------
__device__ float g_h[Bb * Hh];       // hidden state  [256][512]
__device__ float g_zA[Bb * BBd];     // backbone ping  [256][256]
__device__ float g_zB[Bb * BBd];     // backbone pong  [256][256]
__device__ int   g_abort = 0;        // watchdog flag

// group barriers: batch-row groups are fully independent pipelines.
struct __align__(128) Bar { unsigned count; unsigned gen; unsigned pad[30]; };
__device__ Bar g_bar16[8];           // per-m1 groups (16 CTAs each)
__device__ Bar g_bar32[4];           // per-mh groups (32 CTAs each)

// ---------------- group barrier: hard spin + watchdog ----------------------
__device__ __forceinline__ void group_barrier(Bar* b, unsigned nctas) {
    __syncthreads();
    if (threadIdx.x == 0) {
        if (!*(volatile int*)&g_abort) {
            __threadfence();
            volatile unsigned* vgen = (volatile unsigned*)&b->gen;
            unsigned gen = *vgen;                 // read BEFORE arriving
            unsigned rank = atomicAdd(&b->count, 1);
            if (rank == nctas - 1) {
                atomicExch(&b->count, 0);
                __threadfence();
                atomicAdd((unsigned*)&b->gen, 1);
            } else {
                long long t0 = clock64();
                unsigned it = 0;
                while (*vgen == gen) {
                    if (((++it) & 255u) == 0u) {
                        if (*(volatile int*)&g_abort) break;
                        if (clock64() - t0 > 2000000000LL) {  // ~1s: residency fail
                            atomicExch(&g_abort, 1);
                            break;
                        }
                    }
                }
            }
            __threadfence();
        }
    }
    __syncthreads();
}

// ---------------- packed f32x2 FMA helpers ---------------------------------
__device__ __forceinline__ u64 ffma2(u64 a, u64 b, u64 c) {
    u64 d;
    asm("fma.rn.f32x2 %0, %1, %2, %3;" : "=l"(d) : "l"(a), "l"(b), "l"(c));
    return d;
}
__device__ __forceinline__ float sum2(u64 v) {
    union { u64 u; float2 f; } cv; cv.u = v;
    return cv.f.x + cv.f.y;
}

// MAC over NQ 16-byte k-units: 2 activation rows (global) x 1 weight col (smem).
// a0/a1: global row pointers; w: smem weight row (k-contiguous).
template<int NQ>
__device__ __forceinline__ void mac2row(const float* a0g, const float* a1g,
                                        const float* ws,
                                        u64& p0a, u64& p0b, u64& p1a, u64& p1b) {
    const ulonglong2* a0 = (const ulonglong2*)a0g;
    const ulonglong2* a1 = (const ulonglong2*)a1g;
    const ulonglong2* w  = (const ulonglong2*)ws;
#pragma unroll 16
    for (int q = 0; q < NQ; q++) {
        ulonglong2 wv = w[q];
        ulonglong2 x0 = a0[q];
        ulonglong2 x1 = a1[q];
        p0a = ffma2(x0.x, wv.x, p0a);
        p0b = ffma2(x0.y, wv.y, p0b);
        p1a = ffma2(x1.x, wv.x, p1a);
        p1b = ffma2(x1.y, wv.y, p1b);
    }
}

__global__ void __launch_bounds__(NTHR, 1)
lnn_kernel(const float* __restrict__ x,     const float* __restrict__ ts,
           const float* __restrict__ Wb0,   const float* __restrict__ bb0,
           const float* __restrict__ Wbs,   const float* __restrict__ bbs,
           const float* __restrict__ W_ff1, const float* __restrict__ b_ff1,
           const float* __restrict__ W_ff2, const float* __restrict__ b_ff2,
           const float* __restrict__ W_ta,  const float* __restrict__ b_ta,
           const float* __restrict__ W_tb,  const float* __restrict__ b_tb,
           const float* __restrict__ W_out, const float* __restrict__ b_out,
           float* __restrict__ out) {
    extern __shared__ float smf[];
    const int tid = threadIdx.x;
    const int g   = blockIdx.x;
    const int n   = tid & 15;     // column within 16-wide N slice
    const int mg  = tid >> 4;     // 0..15
    const int m1  = g >> 4;       // stage1/backbone: 8 M-tiles of 32
    const int n1  = g & 15;       // 16 N-slices of 16
    const int mh  = g >> 5;       // heads: 4 M-tiles of 64
    const int jh  = g & 31;       // heads: 32 j-slices of 16

    Bar* barS = &g_bar16[m1];     // 16-CTA scope (32 shared rows)
    Bar* barH = &g_bar32[mh];     // 32-CTA scope (64 shared rows)

    if (tid == 0) *(volatile int*)&g_abort = 0;   // reset watchdog (benign race)

    // ---- one-time: weight slices into SMEM (transposed, k contiguous) ----
    for (int e = tid; e < 16 * 768; e += NTHR) {
        int nn = e / 768, k = e % 768;
        smf[OFF_W1 + nn * P1 + k] = Wb0[k * BBd + n1 * 16 + nn];
    }
    for (int e = tid; e < 3 * 16 * 256; e += NTHR) {
        int l = e / (16 * 256);
        int r = e % (16 * 256);
        int nn = r / 256, k = r % 256;
        smf[OFF_WB + (l * 16 + nn) * PB + k] = Wbs[(l * BBd + k) * BBd + n1 * 16 + nn];
    }
    for (int e = tid; e < 64 * 256; e += NTHR) {
        int r = e / 256, k = e % 256;
        int hh = r / 16, ng = r % 16;
        const float* Wsrc = (hh == 0) ? W_ff1 : (hh == 1) ? W_ff2 : (hh == 2) ? W_ta : W_tb;
        smf[OFF_WH + r * PB + k] = Wsrc[k * Hh + jh * 16 + ng];
    }
    // biases into registers
    float bz0   = bb0[n1 * 16 + n];
    float bb_l0 = bbs[0 * BBd + n1 * 16 + n];
    float bb_l1 = bbs[1 * BBd + n1 * 16 + n];
    float bb_l2 = bbs[2 * BBd + n1 * 16 + n];
    float bf1   = b_ff1[jh * 16 + n];
    float bf2   = b_ff2[jh * 16 + n];
    float bta   = b_ta [jh * 16 + n];
    float btb   = b_tb [jh * 16 + n];

    // zero hidden state rows owned by this CTA (rows 2g, 2g+1 — group-local)
    for (int e = tid; e < 1024; e += NTHR) g_h[g * 1024 + e] = 0.0f;
    __syncthreads();
    group_barrier(barS, 16);

    const int r2  = m1 * 32 + mg * 2;          // stage1/backbone row pair base
    const int r4  = mh * 64 + mg * 4;          // heads row quad base
    const int jS  = n1 * 16 + n;               // stage1/backbone output col
    const int jHd = jh * 16 + n;               // heads output col

    for (int t = 0; t < Ss; t++) {
        if (*(volatile int*)&g_abort) break;

        // ===== stage 1: z0 = tanh([x_t,h] @ Wb0 + bb0), sync-free =====
        {
            u64 p0a = 0, p0b = 0, p1a = 0, p1b = 0;
            const float* x0 = x + ((size_t)r2 * Ss + t) * Ii;
            const float* x1 = x0 + (size_t)Ss * Ii;
            mac2row<64>(x0, x1, smf + OFF_W1 + n * P1, p0a, p0b, p1a, p1b);
            const float* h0 = g_h + r2 * Hh;
            const float* h1 = h0 + Hh;
            mac2row<128>(h0, h1, smf + OFF_W1 + n * P1 + 256, p0a, p0b, p1a, p1b);
            float acc0 = sum2(p0a) + sum2(p0b);
            float acc1 = sum2(p1a) + sum2(p1b);
            g_zA[r2 * BBd + jS]       = tanhf(acc0 + bz0);
            g_zA[(r2 + 1) * BBd + jS] = tanhf(acc1 + bz0);
        }
        group_barrier(barS, 16);

        // ===== backbone: 3x z = tanh(z @ Wbs[l] + bbs[l]), sync-free =====
#pragma unroll
        for (int l = 0; l < 3; l++) {
            const float* zin = (l == 1) ? g_zB : g_zA;
            float*       zot = (l == 1) ? g_zA : g_zB;
            u64 p0a = 0, p0b = 0, p1a = 0, p1b = 0;
            const float* z0 = zin + r2 * BBd;
            mac2row<64>(z0, z0 + BBd, smf + OFF_WB + (l * 16 + n) * PB,
                        p0a, p0b, p1a, p1b);
            float bl = (l == 0) ? bb_l0 : (l == 1) ? bb_l1 : bb_l2;
            float acc0 = sum2(p0a) + sum2(p0b);
            float acc1 = sum2(p1a) + sum2(p1b);
            zot[r2 * BBd + jS]       = tanhf(acc0 + bl);
            zot[(r2 + 1) * BBd + jS] = tanhf(acc1 + bl);
            if (l < 2) group_barrier(barS, 16);
            else       group_barrier(barH, 32);   // heads scope spans 2 m1-tiles
        }

        // ===== heads: ff1/ff2/ta/tb + gate -> new h, sync-free =====
        {
            u64 acc[4][4];
#pragma unroll
            for (int i = 0; i < 4; i++)
#pragma unroll
                for (int hh = 0; hh < 4; hh++) acc[i][hh] = 0;

            const ulonglong2* a0 = (const ulonglong2*)(g_zB + (r4 + 0) * BBd);
            const ulonglong2* a1 = (const ulonglong2*)(g_zB + (r4 + 1) * BBd);
            const ulonglong2* a2 = (const ulonglong2*)(g_zB + (r4 + 2) * BBd);
            const ulonglong2* a3 = (const ulonglong2*)(g_zB + (r4 + 3) * BBd);
            const ulonglong2* w0 = (const ulonglong2*)(smf + OFF_WH + (0 * 16 + n) * PB);
            const ulonglong2* w1 = (const ulonglong2*)(smf + OFF_WH + (1 * 16 + n) * PB);
            const ulonglong2* w2 = (const ulonglong2*)(smf + OFF_WH + (2 * 16 + n) * PB);
            const ulonglong2* w3 = (const ulonglong2*)(smf + OFF_WH + (3 * 16 + n) * PB);
#pragma unroll 8
            for (int q = 0; q < 64; q++) {
                ulonglong2 wv0 = w0[q], wv1 = w1[q], wv2 = w2[q], wv3 = w3[q];
                ulonglong2 av;
                av = a0[q];
                acc[0][0] = ffma2(av.x, wv0.x, acc[0][0]); acc[0][0] = ffma2(av.y, wv0.y, acc[0][0]);
                acc[0][1] = ffma2(av.x, wv1.x, acc[0][1]); acc[0][1] = ffma2(av.y, wv1.y, acc[0][1]);
                acc[0][2] = ffma2(av.x, wv2.x, acc[0][2]); acc[0][2] = ffma2(av.y, wv2.y, acc[0][2]);
                acc[0][3] = ffma2(av.x, wv3.x, acc[0][3]); acc[0][3] = ffma2(av.y, wv3.y, acc[0][3]);
                av = a1[q];
                acc[1][0] = ffma2(av.x, wv0.x, acc[1][0]); acc[1][0] = ffma2(av.y, wv0.y, acc[1][0]);
                acc[1][1] = ffma2(av.x, wv1.x, acc[1][1]); acc[1][1] = ffma2(av.y, wv1.y, acc[1][1]);
                acc[1][2] = ffma2(av.x, wv2.x, acc[1][2]); acc[1][2] = ffma2(av.y, wv2.y, acc[1][2]);
                acc[1][3] = ffma2(av.x, wv3.x, acc[1][3]); acc[1][3] = ffma2(av.y, wv3.y, acc[1][3]);
                av = a2[q];
                acc[2][0] = ffma2(av.x, wv0.x, acc[2][0]); acc[2][0] = ffma2(av.y, wv0.y, acc[2][0]);
                acc[2][1] = ffma2(av.x, wv1.x, acc[2][1]); acc[2][1] = ffma2(av.y, wv1.y, acc[2][1]);
                acc[2][2] = ffma2(av.x, wv2.x, acc[2][2]); acc[2][2] = ffma2(av.y, wv2.y, acc[2][2]);
                acc[2][3] = ffma2(av.x, wv3.x, acc[2][3]); acc[2][3] = ffma2(av.y, wv3.y, acc[2][3]);
                av = a3[q];
                acc[3][0] = ffma2(av.x, wv0.x, acc[3][0]); acc[3][0] = ffma2(av.y, wv0.y, acc[3][0]);
                acc[3][1] = ffma2(av.x, wv1.x, acc[3][1]); acc[3][1] = ffma2(av.y, wv1.y, acc[3][1]);
                acc[3][2] = ffma2(av.x, wv2.x, acc[3][2]); acc[3][2] = ffma2(av.y, wv2.y, acc[3][2]);
                acc[3][3] = ffma2(av.x, wv3.x, acc[3][3]); acc[3][3] = ffma2(av.y, wv3.y, acc[3][3]);
            }
#pragma unroll
            for (int i = 0; i < 4; i++) {
                int b = r4 + i;
                float tst = ts[(size_t)b * Ss + t];
                float f1  = tanhf(sum2(acc[i][0]) + bf1);
                float f2  = tanhf(sum2(acc[i][1]) + bf2);
                float ta_ = sum2(acc[i][2]) + bta;
                float tb_ = sum2(acc[i][3]) + btb;
                float ti  = 1.0f / (1.0f + expf(-(ta_ * tst + tb_)));
                g_h[b * Hh + jHd] = f1 + ti * (f2 - f1);
            }
        }
        group_barrier(barH, 32);
    }

    // ===== final: out = h_last @ W_out + b_out =====
    // CTA g reads h rows 8*(g>>2)..+8 — inside its mh scope (final barH above).
    {
        int mo = g >> 2, no = g & 3;
        int m  = mo * 8 + (tid >> 5);
        int nn = no * 32 + (tid & 31);
        float acc = b_out[nn];
        const float* hr = g_h + m * Hh;
#pragma unroll 8
        for (int k = 0; k < Hh; k++) acc += hr[k] * W_out[k * Oo + nn];
        out[m * Oo + nn] = acc;
    }
}

extern "C" void kernel_launch(void* const* d_in, const int* in_sizes, int n_in,
                              void* d_out, int out_size) {
    const float* x     = (const float*)d_in[0];
    const float* ts    = (const float*)d_in[1];
    const float* Wb0   = (const float*)d_in[2];
    const float* bb0   = (const float*)d_in[3];
    const float* Wbs   = (const float*)d_in[4];
    const float* bbs   = (const float*)d_in[5];
    const float* W_ff1 = (const float*)d_in[6];
    const float* b_ff1 = (const float*)d_in[7];
    const float* W_ff2 = (const float*)d_in[8];
    const float* b_ff2 = (const float*)d_in[9];
    const float* W_ta  = (const float*)d_in[10];
    const float* b_ta  = (const float*)d_in[11];
    const float* W_tb  = (const float*)d_in[12];
    const float* b_tb  = (const float*)d_in[13];
    const float* W_out = (const float*)d_in[14];
    const float* b_out = (const float*)d_in[15];

    cudaFuncSetAttribute(lnn_kernel, cudaFuncAttributeMaxDynamicSharedMemorySize, SMEM_BYTES);
    lnn_kernel<<<NCTA, NTHR, SMEM_BYTES>>>(x, ts, Wb0, bb0, Wbs, bbs,
                                           W_ff1, b_ff1, W_ff2, b_ff2,
                                           W_ta, b_ta, W_tb, b_tb,
                                           W_out, b_out, (float*)d_out);
}